// round 7
// baseline (speedup 1.0000x reference)
#include <cuda_runtime.h>
#include <cuda_bf16.h>
#include <cstdint>

#define NN 2048
#define DD 64

// ---------------- device scratch ----------------
__device__ float g_A[NN * DD];                       // A[i] = x_i @ W1[:64] + b1
__device__ float g_B[NN * DD];                       // B[j] = x_j @ W1[64:]
__device__ __align__(16) unsigned short g_W2Th[64 * 72];  // W2^T hi, [n][k] pitch 72
__device__ __align__(16) unsigned short g_W2Tl[64 * 72];  // W2^T lo
__device__ __align__(16) unsigned short g_W3Th[16 * 72];  // W3^T hi
__device__ __align__(16) unsigned short g_W3Tl[16 * 72];  // W3^T lo

// ---------------- helpers ----------------
__device__ __forceinline__ uint32_t smem_u32(const void* p) {
    uint32_t a;
    asm("{ .reg .u64 t; cvta.to.shared.u64 t, %1; cvt.u32.u64 %0, t; }" : "=r"(a) : "l"(p));
    return a;
}
__device__ __forceinline__ uint32_t packbf(float hi, float lo) {
    uint32_t r; asm("cvt.rn.bf16x2.f32 %0, %1, %2;" : "=r"(r) : "f"(hi), "f"(lo)); return r;
}
__device__ __forceinline__ float resid(float v) {
    return v - __uint_as_float(__float_as_uint(v) & 0xFFFF0000u);
}

#define LDSM_X4(r0, r1, r2, r3, addr) \
    asm volatile("ldmatrix.sync.aligned.m8n8.x4.shared.b16 {%0,%1,%2,%3}, [%4];" \
        : "=r"(r0), "=r"(r1), "=r"(r2), "=r"(r3) : "r"(addr))

__device__ __forceinline__ void mma_bf16(float* c, uint32_t a0, uint32_t a1,
                                         uint32_t a2, uint32_t a3,
                                         uint32_t b0, uint32_t b1) {
    asm volatile(
        "mma.sync.aligned.m16n8k16.row.col.f32.bf16.bf16.f32 "
        "{%0,%1,%2,%3}, {%4,%5,%6,%7}, {%8,%9}, {%0,%1,%2,%3};"
        : "+f"(c[0]), "+f"(c[1]), "+f"(c[2]), "+f"(c[3])
        : "r"(a0), "r"(a1), "r"(a2), "r"(a3), "r"(b0), "r"(b1));
}

// ---------------- Kernel 1: precompute A/B rows + weight tiles ----------------
__global__ void precompute_kernel(const float* __restrict__ X,
                                  const float* __restrict__ W1,
                                  const float* __restrict__ b1,
                                  const float* __restrict__ W2,
                                  const float* __restrict__ We,
                                  const float* __restrict__ Wt) {
    if (blockIdx.x < NN) {
        __shared__ float xs[DD];
        const int i = blockIdx.x;
        const int d = threadIdx.x;
        xs[d] = X[i * DD + d];
        __syncthreads();
        float a = b1[d], b = 0.f;
#pragma unroll 8
        for (int k = 0; k < DD; k++) {
            const float xv = xs[k];
            a = fmaf(xv, __ldg(&W1[k * DD + d]), a);
            b = fmaf(xv, __ldg(&W1[(DD + k) * DD + d]), b);
        }
        g_A[i * DD + d] = a;
        g_B[i * DD + d] = b;
    } else {
        const int t = threadIdx.x;
        for (int idx = t; idx < 64 * 72; idx += 64) {
            const int n = idx / 72, k = idx % 72;
            float v = (k < 64) ? W2[k * 64 + n] : 0.f;
            __nv_bfloat16 h = __float2bfloat16_rn(v);
            g_W2Th[idx] = __bfloat16_as_ushort(h);
            g_W2Tl[idx] = __bfloat16_as_ushort(__float2bfloat16_rn(v - __bfloat162float(h)));
        }
        for (int idx = t; idx < 16 * 72; idx += 64) {
            const int n = idx / 72, k = idx % 72;
            float v = 0.f;
            if (k < 64) {
                if (n == 0) v = We[k];
                else if (n < 9) v = Wt[k * 8 + n - 1];
            }
            __nv_bfloat16 h = __float2bfloat16_rn(v);
            g_W3Th[idx] = __bfloat16_as_ushort(h);
            g_W3Tl[idx] = __bfloat16_as_ushort(__float2bfloat16_rn(v - __bfloat162float(h)));
        }
    }
}

// ---------------- SMEM layout (dynamic, 106304 B) ----------------
// Ah   [256][72] bf16   @ 0       (36864)
// Al   [256][72] bf16   @ 36864   (36864)
// BH   [64][72]  bf16   @ 73728   (9216)
// BL   [64][72]  bf16   @ 82944   (9216)
// W3hi [16][72]  bf16   @ 92160   (2304)
// W3lo [16][72]  bf16   @ 94464   (2304)
// sOut [256][9]  f32    @ 96768   (9216)
// sB2  [64]      f32    @ 105984  (256)
// sB3  [16]      f32    @ 106240  (64)
#define SMEM_BYTES 106304
#define MT 256   // pairs per block

// ---------------- Kernel 2: main pair kernel ----------------
__global__ __launch_bounds__(256, 1) void edge_main(
    const float* __restrict__ b2,
    const float* __restrict__ be, const float* __restrict__ bt,
    float* __restrict__ out)
{
    extern __shared__ __align__(16) char smem[];
    unsigned short* Ah = (unsigned short*)smem;
    unsigned short* Al = (unsigned short*)(smem + 36864);
    unsigned short* BH = (unsigned short*)(smem + 73728);
    unsigned short* W3 = (unsigned short*)(smem + 92160);
    float* sOut = (float*)(smem + 96768);
    float* sB2  = (float*)(smem + 105984);
    float* sB3  = (float*)(smem + 106240);

    const int i  = blockIdx.y;
    const int jt = blockIdx.x;
    int jlo = jt * MT; if (i + 1 > jlo) jlo = i + 1;
    int jhi = jt * MT + MT; if (jhi > NN) jhi = NN;
    if (jlo >= jhi) return;
    const int cnt = jhi - jlo;

    const int tid  = threadIdx.x;
    const int warp = tid >> 5;
    const int lane = tid & 31;

    // ---- stage weights ----
    {
        const int4* srcH = (const int4*)g_W2Th;
        const int4* srcL = (const int4*)g_W2Tl;
        int4* dstB = (int4*)BH;
        for (int idx = tid; idx < 576; idx += 256) {
            dstB[idx] = srcH[idx];
            dstB[idx + 576] = srcL[idx];
        }
        if (tid < 144) {
            ((int4*)W3)[tid]       = ((const int4*)g_W3Th)[tid];
            ((int4*)W3)[tid + 144] = ((const int4*)g_W3Tl)[tid];
        }
        if (tid < 64) sB2[tid] = b2[tid];
        if (tid < 16) sB3[tid] = (tid == 0) ? be[0] : (tid < 9 ? bt[tid - 1] : 0.f);
    }

    // ---- stage Ah + Al in one pass (h1 = relu(A[i]+B[j])) ----
    {
        const float4* gB4 = (const float4*)g_B;
        const float4* gA4 = (const float4*)g_A;
#pragma unroll
        for (int it = 0; it < 16; it++) {
            const int idx = tid + it * 256;
            const int m = idx >> 4, kq = idx & 15;
            const int j = jlo + m;
            float4 v = make_float4(0.f, 0.f, 0.f, 0.f);
            if (j < jhi) {
                const float4 b4 = gB4[j * 16 + kq];
                const float4 a4 = __ldg(&gA4[i * 16 + kq]);
                v.x = fmaxf(a4.x + b4.x, 0.f);
                v.y = fmaxf(a4.y + b4.y, 0.f);
                v.z = fmaxf(a4.z + b4.z, 0.f);
                v.w = fmaxf(a4.w + b4.w, 0.f);
            }
            uint2 hp, lp;
            hp.x = __byte_perm(__float_as_uint(v.x), __float_as_uint(v.y), 0x7632);
            hp.y = __byte_perm(__float_as_uint(v.z), __float_as_uint(v.w), 0x7632);
            lp.x = packbf(resid(v.y), resid(v.x));
            lp.y = packbf(resid(v.w), resid(v.z));
            *(uint2*)(Ah + m * 72 + kq * 4) = hp;
            *(uint2*)(Al + m * 72 + kq * 4) = lp;
        }
    }
    __syncthreads();

    // ---- fused 3-pass GEMM, 2 m-tiles per warp (B frags shared) ----
    float acc[2][8][4];
#pragma unroll
    for (int mt = 0; mt < 2; mt++)
#pragma unroll
        for (int nt = 0; nt < 8; nt++)
#pragma unroll
            for (int c = 0; c < 4; c++) acc[mt][nt][c] = 0.f;

    const uint32_t arow = (uint32_t)(warp * 32 + (lane & 15)) * 144 + (lane >> 4) * 16;
    const uint32_t ahbase = smem_u32(Ah) + arow;
    // per-lane combined hi/lo B address: lanes 0-15 -> BH, 16-31 -> BL
    const uint32_t bbase = smem_u32(BH) + ((lane >= 16) ? 9216u : 0u)
                         + (uint32_t)(lane & 7) * 144 + ((lane >> 3) & 1) * 16;
    const uint32_t w3base = smem_u32(W3) + ((lane >= 16) ? 2304u : 0u)
                          + (uint32_t)(lane & 7) * 144 + ((lane >> 3) & 1) * 16;

#pragma unroll
    for (int kt = 0; kt < 4; kt++) {
        uint32_t ah[2][4], al[2][4];
        LDSM_X4(ah[0][0], ah[0][1], ah[0][2], ah[0][3], ahbase + kt * 32);
        LDSM_X4(al[0][0], al[0][1], al[0][2], al[0][3], ahbase + 36864 + kt * 32);
        LDSM_X4(ah[1][0], ah[1][1], ah[1][2], ah[1][3], ahbase + 16 * 144 + kt * 32);
        LDSM_X4(al[1][0], al[1][1], al[1][2], al[1][3], ahbase + 36864 + 16 * 144 + kt * 32);
#pragma unroll
        for (int nt = 0; nt < 8; nt++) {
            uint32_t bh0, bh1, bl0, bl1;
            LDSM_X4(bh0, bh1, bl0, bl1, bbase + (uint32_t)nt * 1152 + kt * 32);
#pragma unroll
            for (int mt = 0; mt < 2; mt++) {
                mma_bf16(acc[mt][nt], ah[mt][0], ah[mt][1], ah[mt][2], ah[mt][3], bh0, bh1);
                mma_bf16(acc[mt][nt], ah[mt][0], ah[mt][1], ah[mt][2], ah[mt][3], bl0, bl1);
                mma_bf16(acc[mt][nt], al[mt][0], al[mt][1], al[mt][2], al[mt][3], bh0, bh1);
            }
        }
    }

    // ---- heads: relu+bias in regs, C->A fragment refeed, 3-pass vs W3 hi/lo ----
    {
        const int tg = lane & 3;
#pragma unroll
        for (int mt = 0; mt < 2; mt++) {
            float oacc[2][4];
#pragma unroll
            for (int no = 0; no < 2; no++)
#pragma unroll
                for (int c = 0; c < 4; c++) oacc[no][c] = 0.f;

#pragma unroll
            for (int kt = 0; kt < 4; kt++) {
                const float2 bA = *(const float2*)(sB2 + (2 * kt) * 8 + tg * 2);
                const float2 bB = *(const float2*)(sB2 + (2 * kt + 1) * 8 + tg * 2);
                const float va0 = fmaxf(acc[mt][2 * kt][0] + bA.x, 0.f);
                const float va1 = fmaxf(acc[mt][2 * kt][1] + bA.y, 0.f);
                const float va2 = fmaxf(acc[mt][2 * kt][2] + bA.x, 0.f);
                const float va3 = fmaxf(acc[mt][2 * kt][3] + bA.y, 0.f);
                const float vb0 = fmaxf(acc[mt][2 * kt + 1][0] + bB.x, 0.f);
                const float vb1 = fmaxf(acc[mt][2 * kt + 1][1] + bB.y, 0.f);
                const float vb2 = fmaxf(acc[mt][2 * kt + 1][2] + bB.x, 0.f);
                const float vb3 = fmaxf(acc[mt][2 * kt + 1][3] + bB.y, 0.f);
                const uint32_t a0 = __byte_perm(__float_as_uint(va0), __float_as_uint(va1), 0x7632);
                const uint32_t a1 = __byte_perm(__float_as_uint(va2), __float_as_uint(va3), 0x7632);
                const uint32_t a2 = __byte_perm(__float_as_uint(vb0), __float_as_uint(vb1), 0x7632);
                const uint32_t a3 = __byte_perm(__float_as_uint(vb2), __float_as_uint(vb3), 0x7632);
                const uint32_t la0 = packbf(resid(va1), resid(va0));
                const uint32_t la1 = packbf(resid(va3), resid(va2));
                const uint32_t la2 = packbf(resid(vb1), resid(vb0));
                const uint32_t la3 = packbf(resid(vb3), resid(vb2));
#pragma unroll
                for (int no = 0; no < 2; no++) {
                    uint32_t bh0, bh1, bl0, bl1;
                    LDSM_X4(bh0, bh1, bl0, bl1, w3base + (uint32_t)no * 1152 + kt * 32);
                    mma_bf16(oacc[no], a0, a1, a2, a3, bh0, bh1);
                    mma_bf16(oacc[no], a0, a1, a2, a3, bl0, bl1);
                    mma_bf16(oacc[no], la0, la1, la2, la3, bh0, bh1);
                }
            }

            // store to sOut (pitch 9): cols 0-7 from tile 0, col 8 from tile 1
            const int r0 = warp * 32 + mt * 16 + (lane >> 2);
            const int r1 = r0 + 8;
            const int c0 = tg * 2;
            sOut[r0 * 9 + c0]     = oacc[0][0] + sB3[c0];
            sOut[r0 * 9 + c0 + 1] = oacc[0][1] + sB3[c0 + 1];
            sOut[r1 * 9 + c0]     = oacc[0][2] + sB3[c0];
            sOut[r1 * 9 + c0 + 1] = oacc[0][3] + sB3[c0 + 1];
            if (tg == 0) {
                sOut[r0 * 9 + 8] = oacc[1][0] + sB3[8];
                sOut[r1 * 9 + 8] = oacc[1][2] + sB3[8];
            }
        }
    }
    __syncthreads();

    // ---- packed-triu contiguous store ----
    const size_t pair0 = (size_t)i * (2 * NN - i - 1) / 2 + (size_t)(jlo - i - 1);
    float* gdst = out + pair0 * 9;
    const int tot = cnt * 9;
    for (int idx = tid; idx < tot; idx += 256) gdst[idx] = sOut[idx];
}

extern "C" void kernel_launch(void* const* d_in, const int* in_sizes, int n_in,
                              void* d_out, int out_size) {
    (void)in_sizes; (void)n_in; (void)out_size;
    const float* X  = (const float*)d_in[0];
    const float* W1 = (const float*)d_in[1];
    const float* b1 = (const float*)d_in[2];
    const float* W2 = (const float*)d_in[3];
    const float* b2 = (const float*)d_in[4];
    const float* We = (const float*)d_in[5];
    const float* be = (const float*)d_in[6];
    const float* Wt = (const float*)d_in[7];
    const float* bt = (const float*)d_in[8];
    float* out = (float*)d_out;

    cudaFuncSetAttribute(edge_main, cudaFuncAttributeMaxDynamicSharedMemorySize, SMEM_BYTES);

    precompute_kernel<<<NN + 1, DD>>>(X, W1, b1, W2, We, Wt);

    dim3 grid(NN / MT, NN);
    edge_main<<<grid, 256, SMEM_BYTES>>>(b2, be, bt, out);
}

// round 8
// speedup vs baseline: 1.1047x; 1.1047x over previous
#include <cuda_runtime.h>
#include <cuda_bf16.h>
#include <cstdint>

#define NN 2048
#define DD 64

// ---------------- device scratch ----------------
__device__ float g_A[NN * DD];                       // A[i] = x_i @ W1[:64] + b1
__device__ float g_B[NN * DD];                       // B[j] = x_j @ W1[64:]
__device__ __align__(16) unsigned short g_W2Th[64 * 72];  // W2^T hi, [n][k] pitch 72
__device__ __align__(16) unsigned short g_W2Tl[64 * 72];  // W2^T lo
__device__ __align__(16) unsigned short g_W3Th[16 * 72];  // W3^T hi
__device__ __align__(16) unsigned short g_W3Tl[16 * 72];  // W3^T lo

// ---------------- helpers ----------------
__device__ __forceinline__ uint32_t smem_u32(const void* p) {
    uint32_t a;
    asm("{ .reg .u64 t; cvta.to.shared.u64 t, %1; cvt.u32.u64 %0, t; }" : "=r"(a) : "l"(p));
    return a;
}
__device__ __forceinline__ uint32_t packbf(float hi, float lo) {
    uint32_t r; asm("cvt.rn.bf16x2.f32 %0, %1, %2;" : "=r"(r) : "f"(hi), "f"(lo)); return r;
}
__device__ __forceinline__ float resid(float v) {
    return v - __uint_as_float(__float_as_uint(v) & 0xFFFF0000u);
}

#define LDSM_X4(r0, r1, r2, r3, addr) \
    asm volatile("ldmatrix.sync.aligned.m8n8.x4.shared.b16 {%0,%1,%2,%3}, [%4];" \
        : "=r"(r0), "=r"(r1), "=r"(r2), "=r"(r3) : "r"(addr))

__device__ __forceinline__ void mma_bf16(float* c, uint32_t a0, uint32_t a1,
                                         uint32_t a2, uint32_t a3,
                                         uint32_t b0, uint32_t b1) {
    asm volatile(
        "mma.sync.aligned.m16n8k16.row.col.f32.bf16.bf16.f32 "
        "{%0,%1,%2,%3}, {%4,%5,%6,%7}, {%8,%9}, {%0,%1,%2,%3};"
        : "+f"(c[0]), "+f"(c[1]), "+f"(c[2]), "+f"(c[3])
        : "r"(a0), "r"(a1), "r"(a2), "r"(a3), "r"(b0), "r"(b1));
}

// ---------------- Kernel 1: precompute A/B rows + weight tiles ----------------
__global__ void precompute_kernel(const float* __restrict__ X,
                                  const float* __restrict__ W1,
                                  const float* __restrict__ b1,
                                  const float* __restrict__ W2,
                                  const float* __restrict__ We,
                                  const float* __restrict__ Wt) {
    if (blockIdx.x < NN) {
        __shared__ float xs[DD];
        const int i = blockIdx.x;
        const int d = threadIdx.x;
        xs[d] = X[i * DD + d];
        __syncthreads();
        float a = b1[d], b = 0.f;
#pragma unroll 8
        for (int k = 0; k < DD; k++) {
            const float xv = xs[k];
            a = fmaf(xv, __ldg(&W1[k * DD + d]), a);
            b = fmaf(xv, __ldg(&W1[(DD + k) * DD + d]), b);
        }
        g_A[i * DD + d] = a;
        g_B[i * DD + d] = b;
    } else {
        const int t = threadIdx.x;
        for (int idx = t; idx < 64 * 72; idx += 64) {
            const int n = idx / 72, k = idx % 72;
            float v = (k < 64) ? W2[k * 64 + n] : 0.f;
            __nv_bfloat16 h = __float2bfloat16_rn(v);
            g_W2Th[idx] = __bfloat16_as_ushort(h);
            g_W2Tl[idx] = __bfloat16_as_ushort(__float2bfloat16_rn(v - __bfloat162float(h)));
        }
        for (int idx = t; idx < 16 * 72; idx += 64) {
            const int n = idx / 72, k = idx % 72;
            float v = 0.f;
            if (k < 64) {
                if (n == 0) v = We[k];
                else if (n < 9) v = Wt[k * 8 + n - 1];
            }
            __nv_bfloat16 h = __float2bfloat16_rn(v);
            g_W3Th[idx] = __bfloat16_as_ushort(h);
            g_W3Tl[idx] = __bfloat16_as_ushort(__float2bfloat16_rn(v - __bfloat162float(h)));
        }
    }
}

// ---------------- SMEM layout (dynamic, 69440 B) ----------------
// Ah    [128][72] bf16   @ 0       (18432)
// Al    [128][72] bf16   @ 18432   (18432)
// BH    [64][72]  bf16   @ 36864   (9216)
// BL    [64][72]  bf16   @ 46080   (9216)
// W3hi  [16][72]  bf16   @ 55296   (2304)
// W3lo  [16][72]  bf16   @ 57600   (2304)
// sOut0 [128][9]  f32    @ 59904   (4608)   (N-warp 0 partial, + biases)
// sOut1 [128][9]  f32    @ 64512   (4608)   (N-warp 1 partial)
// sB2   [64]      f32    @ 69120   (256)
// sB3   [16]      f32    @ 69376   (64)
#define SMEM_BYTES 69440

// ---------------- Kernel 2: main pair kernel ----------------
__global__ __launch_bounds__(256, 2) void edge_main(
    const float* __restrict__ b2,
    const float* __restrict__ be, const float* __restrict__ bt,
    float* __restrict__ out)
{
    extern __shared__ __align__(16) char smem[];
    unsigned short* Ah = (unsigned short*)smem;
    unsigned short* BH = (unsigned short*)(smem + 36864);
    unsigned short* W3 = (unsigned short*)(smem + 55296);
    float* sOut0 = (float*)(smem + 59904);
    float* sOut1 = (float*)(smem + 64512);
    float* sB2   = (float*)(smem + 69120);
    float* sB3   = (float*)(smem + 69376);

    const int i  = blockIdx.y;
    const int jt = blockIdx.x;
    int jlo = jt * 128; if (i + 1 > jlo) jlo = i + 1;
    int jhi = jt * 128 + 128; if (jhi > NN) jhi = NN;
    if (jlo >= jhi) return;
    const int cnt = jhi - jlo;

    const int tid  = threadIdx.x;
    const int warp = tid >> 5;
    const int lane = tid & 31;
    const int warpM = warp & 3;       // 0-3: rows warpM*32 .. +32
    const int warpN = warp >> 2;      // 0-1: cols warpN*32 .. +32

    // ---- stage weights ----
    {
        const int4* srcH = (const int4*)g_W2Th;
        const int4* srcL = (const int4*)g_W2Tl;
        int4* dstB = (int4*)BH;
        for (int idx = tid; idx < 576; idx += 256) {
            dstB[idx] = srcH[idx];
            dstB[idx + 576] = srcL[idx];
        }
        if (tid < 144) {
            ((int4*)W3)[tid]       = ((const int4*)g_W3Th)[tid];
            ((int4*)W3)[tid + 144] = ((const int4*)g_W3Tl)[tid];
        }
        if (tid < 64) sB2[tid] = b2[tid];
        if (tid < 16) sB3[tid] = (tid == 0) ? be[0] : (tid < 9 ? bt[tid - 1] : 0.f);
    }

    // ---- stage Ah + Al in one pass (h1 = relu(A[i]+B[j])) ----
    {
        const float4* gB4 = (const float4*)g_B;
        const float4* gA4 = (const float4*)g_A;
#pragma unroll
        for (int it = 0; it < 8; it++) {
            const int idx = tid + it * 256;
            const int m = idx >> 4, kq = idx & 15;
            const int j = jlo + m;
            float4 v = make_float4(0.f, 0.f, 0.f, 0.f);
            if (j < jhi) {
                const float4 b4 = gB4[j * 16 + kq];
                const float4 a4 = __ldg(&gA4[i * 16 + kq]);
                v.x = fmaxf(a4.x + b4.x, 0.f);
                v.y = fmaxf(a4.y + b4.y, 0.f);
                v.z = fmaxf(a4.z + b4.z, 0.f);
                v.w = fmaxf(a4.w + b4.w, 0.f);
            }
            uint2 hp, lp;
            hp.x = __byte_perm(__float_as_uint(v.x), __float_as_uint(v.y), 0x7632);
            hp.y = __byte_perm(__float_as_uint(v.z), __float_as_uint(v.w), 0x7632);
            lp.x = packbf(resid(v.y), resid(v.x));
            lp.y = packbf(resid(v.w), resid(v.z));
            *(uint2*)(Ah + m * 72 + kq * 4) = hp;
            *(uint2*)(Ah + 128 * 72 + m * 72 + kq * 4) = lp;
        }
    }
    __syncthreads();

    // ---- fused 3-pass GEMM: 32 rows x 32 cols per warp (N split) ----
    float acc[2][4][4];
#pragma unroll
    for (int mt = 0; mt < 2; mt++)
#pragma unroll
        for (int nt = 0; nt < 4; nt++)
#pragma unroll
            for (int c = 0; c < 4; c++) acc[mt][nt][c] = 0.f;

    const uint32_t ahbase = smem_u32(Ah)
                          + (uint32_t)(warpM * 32 + (lane & 15)) * 144 + (lane >> 4) * 16;
    // per-lane combined hi/lo B address: lanes 0-15 -> BH, 16-31 -> BL
    const uint32_t bbase = smem_u32(BH) + ((lane >= 16) ? 9216u : 0u)
                         + (uint32_t)warpN * 32 * 144
                         + (uint32_t)(lane & 7) * 144 + ((lane >> 3) & 1) * 16;
    const uint32_t w3base = smem_u32(W3) + ((lane >= 16) ? 2304u : 0u)
                          + (uint32_t)(lane & 7) * 144 + ((lane >> 3) & 1) * 16;

#pragma unroll
    for (int kt = 0; kt < 4; kt++) {
        uint32_t ah[2][4], al[2][4];
        LDSM_X4(ah[0][0], ah[0][1], ah[0][2], ah[0][3], ahbase + kt * 32);
        LDSM_X4(al[0][0], al[0][1], al[0][2], al[0][3], ahbase + 18432 + kt * 32);
        LDSM_X4(ah[1][0], ah[1][1], ah[1][2], ah[1][3], ahbase + 2304 + kt * 32);
        LDSM_X4(al[1][0], al[1][1], al[1][2], al[1][3], ahbase + 18432 + 2304 + kt * 32);
#pragma unroll
        for (int nt = 0; nt < 4; nt++) {
            uint32_t bh0, bh1, bl0, bl1;
            LDSM_X4(bh0, bh1, bl0, bl1, bbase + (uint32_t)nt * 1152 + kt * 32);
#pragma unroll
            for (int mt = 0; mt < 2; mt++) {
                mma_bf16(acc[mt][nt], ah[mt][0], ah[mt][1], ah[mt][2], ah[mt][3], bh0, bh1);
                mma_bf16(acc[mt][nt], ah[mt][0], ah[mt][1], ah[mt][2], ah[mt][3], bl0, bl1);
                mma_bf16(acc[mt][nt], al[mt][0], al[mt][1], al[mt][2], al[mt][3], bh0, bh1);
            }
        }
    }

    // ---- heads (k-partial per N-warp): relu+bias in regs, C->A refeed ----
    {
        const int tg = lane & 3;
        const int n0 = warpN * 32;
        float* sOutP = warpN ? sOut1 : sOut0;
#pragma unroll
        for (int mt = 0; mt < 2; mt++) {
            float oacc[2][4];
#pragma unroll
            for (int no = 0; no < 2; no++)
#pragma unroll
                for (int c = 0; c < 4; c++) oacc[no][c] = 0.f;

#pragma unroll
            for (int t = 0; t < 2; t++) {
                const int kh = warpN * 2 + t;   // global heads k-tile (of 4)
                const float2 bA = *(const float2*)(sB2 + n0 + (2 * t) * 8 + tg * 2);
                const float2 bB = *(const float2*)(sB2 + n0 + (2 * t + 1) * 8 + tg * 2);
                const float va0 = fmaxf(acc[mt][2 * t][0] + bA.x, 0.f);
                const float va1 = fmaxf(acc[mt][2 * t][1] + bA.y, 0.f);
                const float va2 = fmaxf(acc[mt][2 * t][2] + bA.x, 0.f);
                const float va3 = fmaxf(acc[mt][2 * t][3] + bA.y, 0.f);
                const float vb0 = fmaxf(acc[mt][2 * t + 1][0] + bB.x, 0.f);
                const float vb1 = fmaxf(acc[mt][2 * t + 1][1] + bB.y, 0.f);
                const float vb2 = fmaxf(acc[mt][2 * t + 1][2] + bB.x, 0.f);
                const float vb3 = fmaxf(acc[mt][2 * t + 1][3] + bB.y, 0.f);
                const uint32_t a0 = __byte_perm(__float_as_uint(va0), __float_as_uint(va1), 0x7632);
                const uint32_t a1 = __byte_perm(__float_as_uint(va2), __float_as_uint(va3), 0x7632);
                const uint32_t a2 = __byte_perm(__float_as_uint(vb0), __float_as_uint(vb1), 0x7632);
                const uint32_t a3 = __byte_perm(__float_as_uint(vb2), __float_as_uint(vb3), 0x7632);
                const uint32_t la0 = packbf(resid(va1), resid(va0));
                const uint32_t la1 = packbf(resid(va3), resid(va2));
                const uint32_t la2 = packbf(resid(vb1), resid(vb0));
                const uint32_t la3 = packbf(resid(vb3), resid(vb2));
#pragma unroll
                for (int no = 0; no < 2; no++) {
                    uint32_t bh0, bh1, bl0, bl1;
                    LDSM_X4(bh0, bh1, bl0, bl1,
                            w3base + (uint32_t)no * 1152 + (uint32_t)kh * 32);
                    mma_bf16(oacc[no], a0, a1, a2, a3, bh0, bh1);
                    mma_bf16(oacc[no], a0, a1, a2, a3, bl0, bl1);
                    mma_bf16(oacc[no], la0, la1, la2, la3, bh0, bh1);
                }
            }

            // partial store (pitch 9): cols 0-7 from tile 0, col 8 from tile 1.
            // N-warp 0 folds the head biases in; N-warp 1 stores raw partial.
            const int r0 = warpM * 32 + mt * 16 + (lane >> 2);
            const int r1 = r0 + 8;
            const int c0 = tg * 2;
            const float be0 = warpN ? 0.f : sB3[c0];
            const float be1 = warpN ? 0.f : sB3[c0 + 1];
            sOutP[r0 * 9 + c0]     = oacc[0][0] + be0;
            sOutP[r0 * 9 + c0 + 1] = oacc[0][1] + be1;
            sOutP[r1 * 9 + c0]     = oacc[0][2] + be0;
            sOutP[r1 * 9 + c0 + 1] = oacc[0][3] + be1;
            if (tg == 0) {
                const float be8 = warpN ? 0.f : sB3[8];
                sOutP[r0 * 9 + 8] = oacc[1][0] + be8;
                sOutP[r1 * 9 + 8] = oacc[1][2] + be8;
            }
        }
    }
    __syncthreads();

    // ---- combine partials + packed-triu contiguous store ----
    const size_t pair0 = (size_t)i * (2 * NN - i - 1) / 2 + (size_t)(jlo - i - 1);
    float* gdst = out + pair0 * 9;
    const int tot = cnt * 9;
    for (int idx = tid; idx < tot; idx += 256)
        gdst[idx] = sOut0[idx] + sOut1[idx];
}

extern "C" void kernel_launch(void* const* d_in, const int* in_sizes, int n_in,
                              void* d_out, int out_size) {
    (void)in_sizes; (void)n_in; (void)out_size;
    const float* X  = (const float*)d_in[0];
    const float* W1 = (const float*)d_in[1];
    const float* b1 = (const float*)d_in[2];
    const float* W2 = (const float*)d_in[3];
    const float* b2 = (const float*)d_in[4];
    const float* We = (const float*)d_in[5];
    const float* be = (const float*)d_in[6];
    const float* Wt = (const float*)d_in[7];
    const float* bt = (const float*)d_in[8];
    float* out = (float*)d_out;

    cudaFuncSetAttribute(edge_main, cudaFuncAttributeMaxDynamicSharedMemorySize, SMEM_BYTES);

    precompute_kernel<<<NN + 1, DD>>>(X, W1, b1, W2, We, Wt);

    dim3 grid(NN / 128, NN);
    edge_main<<<grid, 256, SMEM_BYTES>>>(b2, be, bt, out);
}

// round 9
// speedup vs baseline: 1.1574x; 1.0478x over previous
#include <cuda_runtime.h>
#include <cuda_bf16.h>
#include <cstdint>

#define NN 2048
#define DD 64

// ---------------- device scratch ----------------
__device__ float g_A[NN * DD];                       // A[i] = x_i @ W1[:64] + b1
__device__ float g_B[NN * DD];                       // B[j] = x_j @ W1[64:]
__device__ __align__(16) unsigned short g_W2Th[64 * 72];  // W2^T hi, [n][k] pitch 72
__device__ __align__(16) unsigned short g_W2Tl[64 * 72];  // W2^T lo
__device__ __align__(16) unsigned short g_W3Th[16 * 72];  // W3^T hi
__device__ __align__(16) unsigned short g_W3Tl[16 * 72];  // W3^T lo

// ---------------- helpers ----------------
__device__ __forceinline__ uint32_t smem_u32(const void* p) {
    uint32_t a;
    asm("{ .reg .u64 t; cvta.to.shared.u64 t, %1; cvt.u32.u64 %0, t; }" : "=r"(a) : "l"(p));
    return a;
}
__device__ __forceinline__ uint32_t packbf(float hi, float lo) {
    uint32_t r; asm("cvt.rn.bf16x2.f32 %0, %1, %2;" : "=r"(r) : "f"(hi), "f"(lo)); return r;
}
__device__ __forceinline__ float resid(float v) {
    return v - __uint_as_float(__float_as_uint(v) & 0xFFFF0000u);
}

#define LDSM_X4(r0, r1, r2, r3, addr) \
    asm volatile("ldmatrix.sync.aligned.m8n8.x4.shared.b16 {%0,%1,%2,%3}, [%4];" \
        : "=r"(r0), "=r"(r1), "=r"(r2), "=r"(r3) : "r"(addr))

__device__ __forceinline__ void mma_bf16(float* c, uint32_t a0, uint32_t a1,
                                         uint32_t a2, uint32_t a3,
                                         uint32_t b0, uint32_t b1) {
    asm volatile(
        "mma.sync.aligned.m16n8k16.row.col.f32.bf16.bf16.f32 "
        "{%0,%1,%2,%3}, {%4,%5,%6,%7}, {%8,%9}, {%0,%1,%2,%3};"
        : "+f"(c[0]), "+f"(c[1]), "+f"(c[2]), "+f"(c[3])
        : "r"(a0), "r"(a1), "r"(a2), "r"(a3), "r"(b0), "r"(b1));
}

// ---------------- Kernel 1: precompute A/B rows + weight tiles ----------------
__global__ void precompute_kernel(const float* __restrict__ X,
                                  const float* __restrict__ W1,
                                  const float* __restrict__ b1,
                                  const float* __restrict__ W2,
                                  const float* __restrict__ We,
                                  const float* __restrict__ Wt) {
    if (blockIdx.x < NN) {
        __shared__ float xs[DD];
        const int i = blockIdx.x;
        const int d = threadIdx.x;
        xs[d] = X[i * DD + d];
        __syncthreads();
        float a = b1[d], b = 0.f;
#pragma unroll 8
        for (int k = 0; k < DD; k++) {
            const float xv = xs[k];
            a = fmaf(xv, __ldg(&W1[k * DD + d]), a);
            b = fmaf(xv, __ldg(&W1[(DD + k) * DD + d]), b);
        }
        g_A[i * DD + d] = a;
        g_B[i * DD + d] = b;
    } else {
        const int t = threadIdx.x;
        for (int idx = t; idx < 64 * 72; idx += 64) {
            const int n = idx / 72, k = idx % 72;
            float v = (k < 64) ? W2[k * 64 + n] : 0.f;
            __nv_bfloat16 h = __float2bfloat16_rn(v);
            g_W2Th[idx] = __bfloat16_as_ushort(h);
            g_W2Tl[idx] = __bfloat16_as_ushort(__float2bfloat16_rn(v - __bfloat162float(h)));
        }
        for (int idx = t; idx < 16 * 72; idx += 64) {
            const int n = idx / 72, k = idx % 72;
            float v = 0.f;
            if (k < 64) {
                if (n == 0) v = We[k];
                else if (n < 9) v = Wt[k * 8 + n - 1];
            }
            __nv_bfloat16 h = __float2bfloat16_rn(v);
            g_W3Th[idx] = __bfloat16_as_ushort(h);
            g_W3Tl[idx] = __bfloat16_as_ushort(__float2bfloat16_rn(v - __bfloat162float(h)));
        }
    }
}

// ---------------- Kernel 2: main pair kernel ----------------
// Static SMEM (~28 KB): B hi/lo + W3 hi/lo + sOut + biases. A operands are
// built DIRECTLY in registers in mma-fragment layout from g_B/g_A (no smem).
__global__ __launch_bounds__(256, 2) void edge_main(
    const float* __restrict__ b2,
    const float* __restrict__ be, const float* __restrict__ bt,
    float* __restrict__ out)
{
    __shared__ __align__(16) unsigned short sBW[2 * 64 * 72];   // BH | BL
    __shared__ __align__(16) unsigned short sW3[2 * 16 * 72];   // W3 hi | lo
    __shared__ __align__(16) float sOut[128 * 9];
    __shared__ __align__(16) float sB2[64];
    __shared__ float sB3[16];

    const int i  = blockIdx.y;
    const int jt = blockIdx.x;
    int jlo = jt * 128; if (i + 1 > jlo) jlo = i + 1;
    int jhi = jt * 128 + 128; if (jhi > NN) jhi = NN;
    if (jlo >= jhi) return;
    const int cnt = jhi - jlo;

    const int tid  = threadIdx.x;
    const int warp = tid >> 5;
    const int lane = tid & 31;

    // ---- stage weights ----
    {
        const int4* srcH = (const int4*)g_W2Th;
        const int4* srcL = (const int4*)g_W2Tl;
        int4* dstB = (int4*)sBW;
        for (int idx = tid; idx < 576; idx += 256) {
            dstB[idx] = srcH[idx];
            dstB[idx + 576] = srcL[idx];
        }
        if (tid < 144) {
            ((int4*)sW3)[tid]       = ((const int4*)g_W3Th)[tid];
            ((int4*)sW3)[tid + 144] = ((const int4*)g_W3Tl)[tid];
        }
        if (tid < 64) sB2[tid] = b2[tid];
        if (tid < 16) sB3[tid] = (tid == 0) ? be[0] : (tid < 9 ? bt[tid - 1] : 0.f);
    }

    // ---- per-lane A-fragment geometry ----
    // m16n8k16 A frag: lane g=lane>>2 holds rows (g, g+8), cols t2=(lane&3)*2, +1, +8, +9.
    const int g  = lane >> 2;
    const int t2 = (lane & 3) * 2;
    const int j0 = jlo + warp * 16 + g;
    const int j1 = j0 + 8;
    const bool ok0 = (j0 < jhi);
    const bool ok1 = (j1 < jhi);
    const float2* B0 = (const float2*)(g_B + (size_t)j0 * 64);
    const float2* B1 = (const float2*)(g_B + (size_t)j1 * 64);

    // preload A[i] columns this lane needs (16 floats)
    float2 aA[4][2];
    {
        const float* Ai = g_A + (size_t)i * 64;
#pragma unroll
        for (int kt = 0; kt < 4; kt++) {
            aA[kt][0] = __ldg((const float2*)(Ai + kt * 16 + t2));
            aA[kt][1] = __ldg((const float2*)(Ai + kt * 16 + t2 + 8));
        }
    }
    __syncthreads();

    // ---- fused 3-pass GEMM, A frags built in registers ----
    float acc[8][4];
#pragma unroll
    for (int nt = 0; nt < 8; nt++)
#pragma unroll
        for (int c = 0; c < 4; c++) acc[nt][c] = 0.f;

    // per-lane combined hi/lo B address: lanes 0-15 -> BH, 16-31 -> BL
    const uint32_t bbase = smem_u32(sBW) + ((lane >= 16) ? 9216u : 0u)
                         + (uint32_t)(lane & 7) * 144 + ((lane >> 3) & 1) * 16;
    const uint32_t w3base = smem_u32(sW3) + ((lane >= 16) ? 2304u : 0u)
                          + (uint32_t)(lane & 7) * 144 + ((lane >> 3) & 1) * 16;

    const float2 zf = make_float2(0.f, 0.f);
#pragma unroll
    for (int kt = 0; kt < 4; kt++) {
        const int c2 = kt * 8 + (t2 >> 1);
        const float2 b00 = ok0 ? B0[c2]     : zf;
        const float2 b01 = ok0 ? B0[c2 + 4] : zf;
        const float2 b10 = ok1 ? B1[c2]     : zf;
        const float2 b11 = ok1 ? B1[c2 + 4] : zf;
        const float v00 = fmaxf(aA[kt][0].x + b00.x, 0.f);
        const float v01 = fmaxf(aA[kt][0].y + b00.y, 0.f);
        const float v02 = fmaxf(aA[kt][1].x + b01.x, 0.f);
        const float v03 = fmaxf(aA[kt][1].y + b01.y, 0.f);
        const float v10 = fmaxf(aA[kt][0].x + b10.x, 0.f);
        const float v11 = fmaxf(aA[kt][0].y + b10.y, 0.f);
        const float v12 = fmaxf(aA[kt][1].x + b11.x, 0.f);
        const float v13 = fmaxf(aA[kt][1].y + b11.y, 0.f);
        const uint32_t ah0 = __byte_perm(__float_as_uint(v00), __float_as_uint(v01), 0x7632);
        const uint32_t ah1 = __byte_perm(__float_as_uint(v10), __float_as_uint(v11), 0x7632);
        const uint32_t ah2 = __byte_perm(__float_as_uint(v02), __float_as_uint(v03), 0x7632);
        const uint32_t ah3 = __byte_perm(__float_as_uint(v12), __float_as_uint(v13), 0x7632);
        const uint32_t al0 = packbf(resid(v01), resid(v00));
        const uint32_t al1 = packbf(resid(v11), resid(v10));
        const uint32_t al2 = packbf(resid(v03), resid(v02));
        const uint32_t al3 = packbf(resid(v13), resid(v12));
#pragma unroll
        for (int nt = 0; nt < 8; nt++) {
            uint32_t bh0, bh1, bl0, bl1;
            LDSM_X4(bh0, bh1, bl0, bl1, bbase + (uint32_t)nt * 1152 + kt * 32);
            mma_bf16(acc[nt], ah0, ah1, ah2, ah3, bh0, bh1);
            mma_bf16(acc[nt], ah0, ah1, ah2, ah3, bl0, bl1);
            mma_bf16(acc[nt], al0, al1, al2, al3, bh0, bh1);
        }
    }

    // ---- heads: relu+bias in regs, C->A fragment refeed, 3-pass vs W3 hi/lo ----
    {
        const int tg = lane & 3;
        float oacc[2][4];
#pragma unroll
        for (int no = 0; no < 2; no++)
#pragma unroll
            for (int c = 0; c < 4; c++) oacc[no][c] = 0.f;

#pragma unroll
        for (int kt = 0; kt < 4; kt++) {
            const float2 bA = *(const float2*)(sB2 + (2 * kt) * 8 + tg * 2);
            const float2 bB = *(const float2*)(sB2 + (2 * kt + 1) * 8 + tg * 2);
            const float va0 = fmaxf(acc[2 * kt][0] + bA.x, 0.f);
            const float va1 = fmaxf(acc[2 * kt][1] + bA.y, 0.f);
            const float va2 = fmaxf(acc[2 * kt][2] + bA.x, 0.f);
            const float va3 = fmaxf(acc[2 * kt][3] + bA.y, 0.f);
            const float vb0 = fmaxf(acc[2 * kt + 1][0] + bB.x, 0.f);
            const float vb1 = fmaxf(acc[2 * kt + 1][1] + bB.y, 0.f);
            const float vb2 = fmaxf(acc[2 * kt + 1][2] + bB.x, 0.f);
            const float vb3 = fmaxf(acc[2 * kt + 1][3] + bB.y, 0.f);
            const uint32_t a0 = __byte_perm(__float_as_uint(va0), __float_as_uint(va1), 0x7632);
            const uint32_t a1 = __byte_perm(__float_as_uint(va2), __float_as_uint(va3), 0x7632);
            const uint32_t a2 = __byte_perm(__float_as_uint(vb0), __float_as_uint(vb1), 0x7632);
            const uint32_t a3 = __byte_perm(__float_as_uint(vb2), __float_as_uint(vb3), 0x7632);
            const uint32_t la0 = packbf(resid(va1), resid(va0));
            const uint32_t la1 = packbf(resid(va3), resid(va2));
            const uint32_t la2 = packbf(resid(vb1), resid(vb0));
            const uint32_t la3 = packbf(resid(vb3), resid(vb2));
#pragma unroll
            for (int no = 0; no < 2; no++) {
                uint32_t bh0, bh1, bl0, bl1;
                LDSM_X4(bh0, bh1, bl0, bl1, w3base + (uint32_t)no * 1152 + kt * 32);
                mma_bf16(oacc[no], a0, a1, a2, a3, bh0, bh1);
                mma_bf16(oacc[no], a0, a1, a2, a3, bl0, bl1);
                mma_bf16(oacc[no], la0, la1, la2, la3, bh0, bh1);
            }
        }

        // store to sOut (pitch 9): cols 0-7 from tile 0, col 8 from tile 1
        const int r0 = warp * 16 + (lane >> 2);
        const int r1 = r0 + 8;
        const int c0 = tg * 2;
        sOut[r0 * 9 + c0]     = oacc[0][0] + sB3[c0];
        sOut[r0 * 9 + c0 + 1] = oacc[0][1] + sB3[c0 + 1];
        sOut[r1 * 9 + c0]     = oacc[0][2] + sB3[c0];
        sOut[r1 * 9 + c0 + 1] = oacc[0][3] + sB3[c0 + 1];
        if (tg == 0) {
            sOut[r0 * 9 + 8] = oacc[1][0] + sB3[8];
            sOut[r1 * 9 + 8] = oacc[1][2] + sB3[8];
        }
    }
    __syncthreads();

    // ---- packed-triu contiguous store ----
    const size_t pair0 = (size_t)i * (2 * NN - i - 1) / 2 + (size_t)(jlo - i - 1);
    float* gdst = out + pair0 * 9;
    const int tot = cnt * 9;
    for (int idx = tid; idx < tot; idx += 256) gdst[idx] = sOut[idx];
}

extern "C" void kernel_launch(void* const* d_in, const int* in_sizes, int n_in,
                              void* d_out, int out_size) {
    (void)in_sizes; (void)n_in; (void)out_size;
    const float* X  = (const float*)d_in[0];
    const float* W1 = (const float*)d_in[1];
    const float* b1 = (const float*)d_in[2];
    const float* W2 = (const float*)d_in[3];
    const float* b2 = (const float*)d_in[4];
    const float* We = (const float*)d_in[5];
    const float* be = (const float*)d_in[6];
    const float* Wt = (const float*)d_in[7];
    const float* bt = (const float*)d_in[8];
    float* out = (float*)d_out;

    precompute_kernel<<<NN + 1, DD>>>(X, W1, b1, W2, We, Wt);

    dim3 grid(NN / 128, NN);
    edge_main<<<grid, 256>>>(b2, be, bt, out);
}